// round 6
// baseline (speedup 1.0000x reference)
#include <cuda_runtime.h>

#define BN 8
#define JN 64
#define CN 32
#define CG 8               // channels per block group (grid.z = CN/CG = 4)
#define HT 8
#define HIMG_ 256
#define WIMG_ 256
#define HW (HIMG_*WIMG_)

// mask_mode: 0 = float mask after res, 1 = uint8 mask packed after res, 2 = no mask
__global__ void __launch_bounds__(256, 3)
roirotate_kernel(const float* __restrict__ image,
                 const float* __restrict__ boxes,
                 float* __restrict__ out,
                 int max_w, int mask_mode)
{
    const int bj = blockIdx.y;               // 0 .. B*J-1
    const int b  = bj >> 6;                  // JN = 64
    const int c0 = blockIdx.z * CG;

    const float* bx = boxes + bj * 5;
    float l   = bx[0];
    float t   = bx[1];
    float r   = bx[2];
    float btm = bx[3];

    float bw = __fsub_rn(r, l);
    float bh = __fsub_rn(btm, t);
    // widths = int32( (bw/bh) * 8 )  in float32 arithmetic, truncation toward zero
    int width = (int)(__fmul_rn(__fdiv_rn(bw, bh), 8.0f));
    float each_w = __fdiv_rn(bw, (float)(width - 1));
    float each_h = __fdiv_rn(bh, 7.0f);   // HEIGHT-1 = 7

    const int chw = HT * max_w;              // per-channel output stride; always %4==0
    const float* imgb = image + (b * CN + c0) * HW;
    float* outb = out + (bj * CN + c0) * chw;

    // ---- mask (only one slice of blocks writes it) ----
    if (blockIdx.x == 0 && blockIdx.z == 0) {
        if (mask_mode == 0) {
            float* maskp = out + BN * JN * CN * chw + bj * max_w;
            for (int k = threadIdx.x; k < max_w; k += blockDim.x)
                maskp[k] = (k < width) ? 1.0f : 0.0f;
        } else if (mask_mode == 1) {
            unsigned char* maskp =
                (unsigned char*)(out + BN * JN * CN * chw) + bj * max_w;
            for (int k = threadIdx.x; k < max_w; k += blockDim.x)
                maskp[k] = (k < width) ? (unsigned char)1 : (unsigned char)0;
        }
    }

    // Quad index over the flattened (i,k) space of one channel slice.
    const int idx = (blockIdx.x * blockDim.x + threadIdx.x) * 4;
    if (idx >= chw) return;

    int i0 = idx / max_w;                     // i0 in [0, 8)
    int k0 = idx - i0 * max_w;

    // ---- all-zero fast path: whole quad in one row and k0 >= width ----
    if (k0 >= width && k0 + 3 < max_w) {
        float4 z = make_float4(0.f, 0.f, 0.f, 0.f);
        float* o = outb + idx;
        #pragma unroll
        for (int c = 0; c < CG; c++) {
            *(float4*)o = z;
            o += chw;
        }
        return;
    }

    // ---- general path: per-element coords/weights, CG channels ----
    int   off00[4], off10[4], off01[4], off11[4];
    float wa[4], wbv[4], wc[4], wd[4];
    bool  valid[4];

    {
        int ii = i0, kk = k0;
        #pragma unroll
        for (int e = 0; e < 4; e++) {
            valid[e] = (kk < width);

            // match JAX float32 mul-then-add exactly (no FMA)
            float x = __fadd_rn(__fmul_rn((float)kk, each_w), l);
            float y = __fadd_rn(__fmul_rn((float)ii, each_h), t);

            float fx = floorf(x), fy = floorf(y);
            int x0 = min(max((int)fx,     0), WIMG_ - 1);
            int x1 = min(max((int)fx + 1, 0), WIMG_ - 1);
            int y0 = min(max((int)fy,     0), HIMG_ - 1);
            int y1 = min(max((int)fy + 1, 0), HIMG_ - 1);

            float x0f = (float)x0, x1f = (float)x1;
            float y0f = (float)y0, y1f = (float)y1;
            wa[e]  = (x1f - x) * (y1f - y);
            wbv[e] = (x1f - x) * (y - y0f);
            wc[e]  = (x - x0f) * (y1f - y);
            wd[e]  = (x - x0f) * (y - y0f);

            off00[e] = y0 * WIMG_ + x0;
            off10[e] = y1 * WIMG_ + x0;
            off01[e] = y0 * WIMG_ + x1;
            off11[e] = y1 * WIMG_ + x1;

            kk++;
            if (kk == max_w) { kk = 0; ii++; }
        }
    }

    const float* ip = imgb;
    float* o = outb + idx;
    #pragma unroll
    for (int c = 0; c < CG; c++) {
        // 16 independent LDGs batched per channel
        float a0 = __ldg(ip + off00[0]), b0 = __ldg(ip + off10[0]),
              p0 = __ldg(ip + off01[0]), d0 = __ldg(ip + off11[0]);
        float a1 = __ldg(ip + off00[1]), b1 = __ldg(ip + off10[1]),
              p1 = __ldg(ip + off01[1]), d1 = __ldg(ip + off11[1]);
        float a2 = __ldg(ip + off00[2]), b2 = __ldg(ip + off10[2]),
              p2 = __ldg(ip + off01[2]), d2 = __ldg(ip + off11[2]);
        float a3 = __ldg(ip + off00[3]), b3 = __ldg(ip + off10[3]),
              p3 = __ldg(ip + off01[3]), d3 = __ldg(ip + off11[3]);

        float4 v;
        v.x = a0 * wa[0] + b0 * wbv[0] + p0 * wc[0] + d0 * wd[0];
        v.y = a1 * wa[1] + b1 * wbv[1] + p1 * wc[1] + d1 * wd[1];
        v.z = a2 * wa[2] + b2 * wbv[2] + p2 * wc[2] + d2 * wd[2];
        v.w = a3 * wa[3] + b3 * wbv[3] + p3 * wc[3] + d3 * wd[3];
        if (!valid[0]) v.x = 0.f;
        if (!valid[1]) v.y = 0.f;
        if (!valid[2]) v.z = 0.f;
        if (!valid[3]) v.w = 0.f;

        *(float4*)o = v;
        ip += HW;
        o  += chw;
    }
}

extern "C" void kernel_launch(void* const* d_in, const int* in_sizes, int n_in,
                              void* d_out, int out_size)
{
    const float* image = (const float*)d_in[0];
    const float* boxes = (const float*)d_in[1];
    float* out = (float*)d_out;

    // Derive max_w from out_size (host-side, no sync needed).
    // res elems per unit max_w: B*J*C*H = 131072 ; mask elems per unit: B*J = 512
    const long long per_res = (long long)BN * JN * CN * HT;     // 131072
    const long long per_fmask = per_res + (long long)BN * JN;   // 131584 (float mask)
    const long long per_u8 = per_res + (long long)BN * JN / 4;  // 131200 (u8 mask packed into f32 elems)

    int max_w, mask_mode;
    long long osz = (long long)out_size;
    if (osz % per_fmask == 0) {
        max_w = (int)(osz / per_fmask);
        mask_mode = 0;
    } else if (osz % per_u8 == 0) {
        max_w = (int)(osz / per_u8);
        mask_mode = 1;
    } else if (osz % per_res == 0) {
        max_w = (int)(osz / per_res);
        mask_mode = 2;
    } else {
        // fallback: assume float-mask layout, round down
        max_w = (int)(osz / per_fmask);
        mask_mode = 0;
    }

    const int block = 256;
    int quads = (HT * max_w) / 4;                 // chw always divisible by 4
    int slices = (quads + block - 1) / block;
    dim3 grid(slices, BN * JN, CN / CG);
    roirotate_kernel<<<grid, block>>>(image, boxes, out, max_w, mask_mode);
}

// round 7
// speedup vs baseline: 1.0169x; 1.0169x over previous
#include <cuda_runtime.h>

#define BN 8
#define JN 64
#define CN 32
#define CG 8               // channels per block group (grid.z = CN/CG = 4)
#define HT 8
#define HIMG_ 256
#define WIMG_ 256
#define HW (HIMG_*WIMG_)

// mask_mode: 0 = float mask after res, 1 = uint8 mask packed after res, 2 = no mask
__global__ void __launch_bounds__(64, 16)
roirotate_kernel(const float* __restrict__ image,
                 const float* __restrict__ boxes,
                 float* __restrict__ out,
                 int max_w, int mask_mode)
{
    const int bj = blockIdx.y;               // 0 .. B*J-1
    const int b  = bj >> 6;                  // JN = 64
    const int c0 = blockIdx.z * CG;

    const float* bx = boxes + bj * 5;
    float l   = bx[0];
    float t   = bx[1];
    float r   = bx[2];
    float btm = bx[3];

    float bw = r - l;
    float bh = btm - t;
    // widths = int32( (bw/bh) * 8 ) in float32 arithmetic — keep this EXACT
    int width = (int)(__fmul_rn(__fdiv_rn(bw, bh), 8.0f));
    float each_w = bw / (float)(width - 1);
    float each_h = bh * (1.0f / 7.0f) ;   // HEIGHT-1 = 7 (tolerance covers rounding)

    const int chw = HT * max_w;              // per-channel output stride
    const float* imgb = image + (b * CN + c0) * HW;
    float* outb = out + (bj * CN + c0) * chw;

    // ---- mask (only one block per bj writes it) ----
    if (blockIdx.x == 0 && blockIdx.z == 0) {
        if (mask_mode == 0) {
            float* maskp = out + BN * JN * CN * chw + bj * max_w;
            for (int k = threadIdx.x; k < max_w; k += blockDim.x)
                maskp[k] = (k < width) ? 1.0f : 0.0f;
        } else if (mask_mode == 1) {
            unsigned char* maskp =
                (unsigned char*)(out + BN * JN * CN * chw) + bj * max_w;
            for (int k = threadIdx.x; k < max_w; k += blockDim.x)
                maskp[k] = (k < width) ? (unsigned char)1 : (unsigned char)0;
        }
    }

    const int k = blockIdx.x * 64 + threadIdx.x;   // this thread's column
    if (k >= max_w) return;

    if (k >= width) {
        // zero tail: 8 channels x 8 rows, coalesced scalar stores
        float* o = outb + k;
        #pragma unroll
        for (int c = 0; c < CG; c++) {
            #pragma unroll
            for (int i = 0; i < HT; i++)
                o[i * max_w] = 0.0f;
            o += chw;
        }
        return;
    }

    // ---- x math: once per thread, shared by all 8 rows and 8 channels ----
    float x = (float)k * each_w + l;
    float fx = floorf(x);
    int x0 = min(max((int)fx,     0), WIMG_ - 1);
    int x1 = min(max((int)fx + 1, 0), WIMG_ - 1);
    float wx0 = x - (float)x0;      // weight for x1 side
    float wx1 = (float)x1 - x;      // weight for x0 side

    #pragma unroll
    for (int i = 0; i < HT; i++) {
        float y = (float)i * each_h + t;
        float fy = floorf(y);
        int y0 = min(max((int)fy,     0), HIMG_ - 1);
        int y1 = min(max((int)fy + 1, 0), HIMG_ - 1);
        float wy0 = y - (float)y0;
        float wy1 = (float)y1 - y;

        float wa = wx1 * wy1;   // (y0,x0)
        float wb = wx1 * wy0;   // (y1,x0)
        float wc = wx0 * wy1;   // (y0,x1)
        float wd = wx0 * wy0;   // (y1,x1)

        const int o00 = y0 * WIMG_ + x0;
        const int o01 = y0 * WIMG_ + x1;
        const int o10 = y1 * WIMG_ + x0;
        const int o11 = y1 * WIMG_ + x1;

        const float* ip = imgb;
        float* o = outb + i * max_w + k;

        // 2 groups of 4 channels: 16 independent LDGs per group
        #pragma unroll
        for (int g = 0; g < CG / 4; g++) {
            float a0 = __ldg(ip + o00),        b0 = __ldg(ip + o10),
                  p0 = __ldg(ip + o01),        d0 = __ldg(ip + o11);
            float a1 = __ldg(ip + HW + o00),   b1 = __ldg(ip + HW + o10),
                  p1 = __ldg(ip + HW + o01),   d1 = __ldg(ip + HW + o11);
            float a2 = __ldg(ip + 2*HW + o00), b2 = __ldg(ip + 2*HW + o10),
                  p2 = __ldg(ip + 2*HW + o01), d2 = __ldg(ip + 2*HW + o11);
            float a3 = __ldg(ip + 3*HW + o00), b3 = __ldg(ip + 3*HW + o10),
                  p3 = __ldg(ip + 3*HW + o01), d3 = __ldg(ip + 3*HW + o11);

            o[0]       = a0 * wa + b0 * wb + p0 * wc + d0 * wd;
            o[chw]     = a1 * wa + b1 * wb + p1 * wc + d1 * wd;
            o[2 * chw] = a2 * wa + b2 * wb + p2 * wc + d2 * wd;
            o[3 * chw] = a3 * wa + b3 * wb + p3 * wc + d3 * wd;

            ip += 4 * HW;
            o  += 4 * chw;
        }
    }
}

extern "C" void kernel_launch(void* const* d_in, const int* in_sizes, int n_in,
                              void* d_out, int out_size)
{
    const float* image = (const float*)d_in[0];
    const float* boxes = (const float*)d_in[1];
    float* out = (float*)d_out;

    // Derive max_w from out_size (host-side, no sync needed).
    // res elems per unit max_w: B*J*C*H = 131072 ; mask elems per unit: B*J = 512
    const long long per_res = (long long)BN * JN * CN * HT;     // 131072
    const long long per_fmask = per_res + (long long)BN * JN;   // 131584 (float mask)
    const long long per_u8 = per_res + (long long)BN * JN / 4;  // 131200 (u8 mask packed into f32 elems)

    int max_w, mask_mode;
    long long osz = (long long)out_size;
    if (osz % per_fmask == 0) {
        max_w = (int)(osz / per_fmask);
        mask_mode = 0;
    } else if (osz % per_u8 == 0) {
        max_w = (int)(osz / per_u8);
        mask_mode = 1;
    } else if (osz % per_res == 0) {
        max_w = (int)(osz / per_res);
        mask_mode = 2;
    } else {
        // fallback: assume float-mask layout, round down
        max_w = (int)(osz / per_fmask);
        mask_mode = 0;
    }

    const int block = 64;
    int slices = (max_w + block - 1) / block;
    dim3 grid(slices, BN * JN, CN / CG);
    roirotate_kernel<<<grid, block>>>(image, boxes, out, max_w, mask_mode);
}

// round 8
// speedup vs baseline: 1.2145x; 1.1943x over previous
#include <cuda_runtime.h>

#define BN 8
#define JN 64
#define CN 32
#define CG 16              // channels per block group (grid.z = CN/CG = 2)
#define HT 8
#define HIMG_ 256
#define WIMG_ 256
#define HW (HIMG_*WIMG_)

// mask_mode: 0 = float mask after res, 1 = uint8 mask packed after res, 2 = no mask
__global__ void roirotate_kernel(const float* __restrict__ image,
                                 const float* __restrict__ boxes,
                                 float* __restrict__ out,
                                 int max_w, float inv_w, int mask_mode)
{
    const int bj = blockIdx.y;               // 0 .. B*J-1
    const int b  = bj >> 6;                  // JN = 64
    const int c0 = blockIdx.z * CG;

    const float* bx = boxes + bj * 5;
    float l   = bx[0];
    float t   = bx[1];
    float r   = bx[2];
    float btm = bx[3];

    float bw = r - l;
    float bh = btm - t;
    // widths = int32( (bw/bh) * 8 ) in float32 arithmetic — keep EXACT
    int width = (int)(__fmul_rn(__fdiv_rn(bw, bh), 8.0f));
    float each_w = bw / (float)(width - 1);
    float each_h = bh * (1.0f / 7.0f);        // HEIGHT-1 = 7

    const int chw = HT * max_w;               // per-channel output stride
    const float* imgb = image + (b * CN + c0) * HW;
    float* outb = out + (bj * CN + c0) * chw;

    // ---- mask (only one slice of blocks writes it) ----
    if (blockIdx.x == 0 && blockIdx.z == 0) {
        if (mask_mode == 0) {
            float* maskp = out + BN * JN * CN * chw + bj * max_w;
            for (int k = threadIdx.x; k < max_w; k += blockDim.x)
                maskp[k] = (k < width) ? 1.0f : 0.0f;
        } else if (mask_mode == 1) {
            unsigned char* maskp =
                (unsigned char*)(out + BN * JN * CN * chw) + bj * max_w;
            for (int k = threadIdx.x; k < max_w; k += blockDim.x)
                maskp[k] = (k < width) ? (unsigned char)1 : (unsigned char)0;
        }
    }

    const int idx = blockIdx.x * blockDim.x + threadIdx.x;   // over HT*max_w
    if (idx >= chw) return;

    // i = idx / max_w, k = idx % max_w  via float reciprocal + exact fixup
    int i = (int)((float)idx * inv_w);
    int k = idx - i * max_w;
    if (k < 0)            { i--; k += max_w; }
    else if (k >= max_w)  { i++; k -= max_w; }

    float* op = outb + idx;                   // == outb + i*max_w + k

    if (k >= width) {
        // masked region -> zeros (buffer poisoned, must write); L2-direct
        float* o = op;
        #pragma unroll
        for (int c = 0; c < CG; c++) { __stcg(o, 0.0f); o += chw; }
        return;
    }

    float x = (float)k * each_w + l;
    float y = (float)i * each_h + t;

    float fx = floorf(x), fy = floorf(y);
    int x0 = min(max((int)fx,     0), WIMG_ - 1);
    int x1 = min(max((int)fx + 1, 0), WIMG_ - 1);
    int y0 = min(max((int)fy,     0), HIMG_ - 1);
    int y1 = min(max((int)fy + 1, 0), HIMG_ - 1);

    float wx0 = x - (float)x0;     // weight for x1 side
    float wx1 = (float)x1 - x;     // weight for x0 side
    float wy0 = y - (float)y0;
    float wy1 = (float)y1 - y;

    float wa = wx1 * wy1;   // (y0,x0)
    float wb = wx1 * wy0;   // (y1,x0)
    float wc = wx0 * wy1;   // (y0,x1)
    float wd = wx0 * wy0;   // (y1,x1)

    const int o00 = y0 * WIMG_ + x0;
    const int o01 = y0 * WIMG_ + x1;
    const int o10 = y1 * WIMG_ + x0;
    const int o11 = y1 * WIMG_ + x1;

    const float* ip = imgb;
    float* o = op;
    #pragma unroll 4
    for (int c = 0; c < CG; c++) {
        float v = __ldg(ip + o00) * wa
                + __ldg(ip + o10) * wb
                + __ldg(ip + o01) * wc
                + __ldg(ip + o11) * wd;
        __stcg(o, v);
        ip += HW;
        o  += chw;
    }
}

extern "C" void kernel_launch(void* const* d_in, const int* in_sizes, int n_in,
                              void* d_out, int out_size)
{
    const float* image = (const float*)d_in[0];
    const float* boxes = (const float*)d_in[1];
    float* out = (float*)d_out;

    // Derive max_w from out_size (host-side, no sync needed).
    // res elems per unit max_w: B*J*C*H = 131072 ; mask elems per unit: B*J = 512
    const long long per_res = (long long)BN * JN * CN * HT;     // 131072
    const long long per_fmask = per_res + (long long)BN * JN;   // 131584 (float mask)
    const long long per_u8 = per_res + (long long)BN * JN / 4;  // 131200 (u8 mask packed into f32 elems)

    int max_w, mask_mode;
    long long osz = (long long)out_size;
    if (osz % per_fmask == 0) {
        max_w = (int)(osz / per_fmask);
        mask_mode = 0;
    } else if (osz % per_u8 == 0) {
        max_w = (int)(osz / per_u8);
        mask_mode = 1;
    } else if (osz % per_res == 0) {
        max_w = (int)(osz / per_res);
        mask_mode = 2;
    } else {
        // fallback: assume float-mask layout, round down
        max_w = (int)(osz / per_fmask);
        mask_mode = 0;
    }

    const int block = 256;
    int slices = (HT * max_w + block - 1) / block;
    dim3 grid(slices, BN * JN, CN / CG);
    float inv_w = 1.0f / (float)max_w;
    roirotate_kernel<<<grid, block>>>(image, boxes, out, max_w, inv_w, mask_mode);
}